// round 16
// baseline (speedup 1.0000x reference)
#include <cuda_runtime.h>
#include <cuda_fp16.h>
#include <cstdint>

#define PB 8
#define PN 2048
#define PD 512
#define PS 4096
#define NROWS 32768
#define K1 2048
#define N1 512
#define K2 512
#define N2 256

// ---- device scratch ----
__device__ __half g_h[PB * PN * PD];              // fp16 h (16.8 MB)
__device__ __half g_W1t[N1 * K1];                 // W1 transposed [n][k]
__device__ __half g_W2t[N2 * K2];                 // W2 transposed [n][k]
__device__ __half g_Y[(size_t)(PB * PN) * 2048];  // per-(node,j) partials (67 MB)

__device__ __forceinline__ float gelu_exact(float x) {
    return 0.5f * x * (1.0f + erff(x * 0.70710678118654752440f));
}
__device__ __forceinline__ float softplus_stable(float x) {
    return fmaxf(x, 0.0f) + log1pf(expf(-fabsf(x)));
}
__device__ __forceinline__ uint32_t smem_u32(const void* p) {
    uint32_t a;
    asm("{ .reg .u64 t; cvta.to.shared.u64 t, %1; cvt.u32.u64 %0, t; }" : "=r"(a) : "l"(p));
    return a;
}
__device__ __forceinline__ void cp16(uint32_t dst, const void* src) {
    asm volatile("cp.async.cg.shared.global [%0], [%1], 16;" :: "r"(dst), "l"(src));
}
#define CP_COMMIT() asm volatile("cp.async.commit_group;" ::: "memory")
#define CP_WAIT(n)  asm volatile("cp.async.wait_group %0;" :: "n"(n) : "memory")

__device__ __forceinline__ void mma_f16(float* d, const uint32_t* a, const uint32_t* b) {
    asm volatile(
        "mma.sync.aligned.m16n8k16.row.col.f32.f16.f16.f32 "
        "{%0,%1,%2,%3}, {%4,%5,%6,%7}, {%8,%9}, {%0,%1,%2,%3};"
        : "+f"(d[0]), "+f"(d[1]), "+f"(d[2]), "+f"(d[3])
        : "r"(a[0]), "r"(a[1]), "r"(a[2]), "r"(a[3]), "r"(b[0]), "r"(b[1]));
}
__device__ __forceinline__ void ldsm4(uint32_t* r, uint32_t addr) {
    asm volatile("ldmatrix.sync.aligned.m8n8.x4.shared.b16 {%0,%1,%2,%3}, [%4];"
        : "=r"(r[0]), "=r"(r[1]), "=r"(r[2]), "=r"(r[3]) : "r"(addr));
}

// tiles with 64 halves (8 x 16B granules) per row, row stride 32 words:
// word = r*32 + 4*(g ^ (r&7))  -> conflict-free for cp.async stores + ldmatrix
__device__ __forceinline__ int t64w(int r, int g) { return r * 32 + 4 * (g ^ (r & 7)); }
// x1 tile: 512 halves (64 granules)/row; XOR low-3 granule bits
__device__ __forceinline__ int xwd_w(int r, int kp) { return r * 256 + (kp ^ ((r & 7) << 2)); }

// ---- prepass kernels ----
__global__ void cvt_h_kernel(__half* __restrict__ dst, const float* __restrict__ src, int n4) {
    for (int i = blockIdx.x * blockDim.x + threadIdx.x; i < n4; i += gridDim.x * blockDim.x) {
        const float4 v = ((const float4*)src)[i];
        __half2 lo = __floats2half2_rn(v.x, v.y);
        __half2 hi = __floats2half2_rn(v.z, v.w);
        ((__half2*)dst)[2 * i]     = lo;
        ((__half2*)dst)[2 * i + 1] = hi;
    }
}
__global__ void transpose_half_kernel(__half* __restrict__ dst, const float* __restrict__ src,
                                      int K, int N) {
    __shared__ __half t[32][33];
    const int k0 = blockIdx.y * 32, n0 = blockIdx.x * 32;
    const int tx = threadIdx.x, ty = threadIdx.y;
    #pragma unroll
    for (int i = 0; i < 32; i += 8)
        t[ty + i][tx] = __float2half_rn(src[(size_t)(k0 + ty + i) * N + n0 + tx]);
    __syncthreads();
    #pragma unroll
    for (int i = 0; i < 32; i += 8)
        dst[(size_t)(n0 + ty + i) * K + k0 + tx] = t[tx][ty + i];
}

// ============================================================================
// Kernel A (reverted to R13 best): Y = h @ W1-blocks per 128x256 tile.
// 512 thr, warp grid 2(m)x8(n), warp tile 64x32, KC=64, 8 stages, 3 buffers.
// ============================================================================
#define PWA0 0
#define PWB0 12288
#define PRE_SMEM_BYTES ((12288 + 24576) * 4)

__global__ void __launch_bounds__(512, 1)
precompute_y_kernel()
{
    extern __shared__ uint32_t smw[];
    const uint32_t sb  = smem_u32(smw);
    const uint32_t sbA = sb + PWA0 * 4;
    const uint32_t sbB = sb + PWB0 * 4;

    const int tid  = threadIdx.x;
    const int lane = tid & 31;
    const int wid  = tid >> 5;
    const int lq   = lane >> 2;
    const int lr   = lane & 3;
    const int wm   = wid >> 3;
    const int wn   = wid & 7;

    const int row0  = blockIdx.x * 128;
    const int nbase = blockIdx.y * 256;
    const int jblk  = nbase >> 9;
    const int dbase = nbase & 511;

    const int l7  = lane & 7;
    const int gha = lane >> 4;
    const int ghb = (lane >> 3) & 1;
    uint32_t abase[4];
    #pragma unroll
    for (int mf = 0; mf < 4; mf++) {
        const int r = wm * 64 + mf * 16 + (lane & 15);
        abase[mf] = (uint32_t)(r * 32) * 4;
    }
    const int bnr = wn * 32 + ((lane >> 4) << 3) + (lane & 7);
    const uint32_t bbase0 = (uint32_t)(bnr * 32) * 4;
    const uint32_t bbase1 = (uint32_t)((bnr + 16) * 32) * 4;

    auto issueA = [&](int buf, int kt) {
        #pragma unroll
        for (int i = 0; i < 2; i++) {
            const int idx = i * 512 + tid;
            const int row = idx >> 3, g = idx & 7;
            cp16(sbA + buf * 16384 + (uint32_t)t64w(row, g) * 4,
                 g_h + (size_t)(row0 + row) * PD + kt + g * 8);
        }
    };
    auto issueB = [&](int buf, int kt) {
        #pragma unroll
        for (int i = 0; i < 4; i++) {
            const int idx = i * 512 + tid;
            const int n = idx >> 3, g = idx & 7;
            cp16(sbB + buf * 32768 + (uint32_t)t64w(n, g) * 4,
                 g_W1t + (size_t)(dbase + n) * K1 + jblk * 512 + kt + g * 8);
        }
    };

    float acc[4][4][4];
    #pragma unroll
    for (int mf = 0; mf < 4; mf++)
        #pragma unroll
        for (int nf = 0; nf < 4; nf++)
            #pragma unroll
            for (int q = 0; q < 4; q++) acc[mf][nf][q] = 0.0f;

    const int NST = PD / 64;   // 8
    issueA(0, 0);  issueB(0, 0);  CP_COMMIT();
    issueA(1, 64); issueB(1, 64); CP_COMMIT();

    for (int s = 0; s < NST; ++s) {
        CP_WAIT(1);
        __syncthreads();
        if (s + 2 < NST) { issueA((s + 2) % 3, (s + 2) * 64); issueB((s + 2) % 3, (s + 2) * 64); }
        CP_COMMIT();

        const uint32_t Ab = sbA + (s % 3) * 16384;
        const uint32_t Bb = sbB + (s % 3) * 32768;
        #pragma unroll
        for (int ks = 0; ks < 4; ++ks) {
            const int sa  = ((2 * ks + gha) ^ l7) * 16;
            const int sbo = ((2 * ks + ghb) ^ l7) * 16;
            uint32_t a[4][4];
            #pragma unroll
            for (int mf = 0; mf < 4; mf++)
                ldsm4(a[mf], Ab + abase[mf] + sa);
            uint32_t bf[4][2];
            {
                uint32_t t4[4];
                ldsm4(t4, Bb + bbase0 + sbo);
                bf[0][0] = t4[0]; bf[0][1] = t4[1];
                bf[1][0] = t4[2]; bf[1][1] = t4[3];
                ldsm4(t4, Bb + bbase1 + sbo);
                bf[2][0] = t4[0]; bf[2][1] = t4[1];
                bf[3][0] = t4[2]; bf[3][1] = t4[3];
            }
            #pragma unroll
            for (int mf = 0; mf < 4; mf++)
                #pragma unroll
                for (int nf = 0; nf < 4; nf++)
                    mma_f16(acc[mf][nf], a[mf], bf[nf]);
        }
    }

    #pragma unroll
    for (int mf = 0; mf < 4; mf++) {
        const int r = row0 + wm * 64 + mf * 16 + lq;
        #pragma unroll
        for (int nf = 0; nf < 4; nf++) {
            const int c = nbase + wn * 32 + nf * 8 + 2 * lr;
            const float* cc = acc[mf][nf];
            *(__half2*)&g_Y[(size_t)r * 2048 + c]       = __floats2half2_rn(cc[0], cc[1]);
            *(__half2*)&g_Y[(size_t)(r + 8) * 2048 + c] = __floats2half2_rn(cc[2], cc[3]);
        }
    }
}

// ============================================================================
// Kernel B: 256 thr, MTILE=32, 2 CTAs/SM. Gather chunks FUSED into the GEMM2
// stage loop: stage s computes on x1 chunk s while chunk s+1 is gathered.
// ============================================================================
#define WX1   0                        // x1: 32 rows x 256 words = 8192
#define WB0s  8192                     // B bufs: 2 x 8192 words (32KB each)
#define WB1S  (WB0s + 16384)           // b1: 512
#define WB2S  (WB1S + 512)             // b2: 256
#define WW3S  (WB2S + 256)             // W3: 256
#define WRED  (WW3S + 256)             // red: 256
#define WNODE (WRED + 256)             // nodes: 128
#define WMODE (WNODE + 128)
#define SC_SMEM_BYTES ((WMODE + 4) * 4)

__global__ void __launch_bounds__(256, 2)
swap_scoring_g(const void* __restrict__ indices_raw,
               const float* __restrict__ b1,
               const float* __restrict__ b2,
               const float* __restrict__ W3,
               const float* __restrict__ b3,
               float* __restrict__ out)
{
    extern __shared__ uint32_t smw[];
    float* b1s = (float*)(smw + WB1S);
    float* b2s = (float*)(smw + WB2S);
    float* w3s = (float*)(smw + WW3S);
    float* red = (float*)(smw + WRED);
    int*   nodes = (int*)(smw + WNODE);

    const uint32_t sb  = smem_u32(smw);
    const uint32_t sbB = sb + WB0s * 4;
    const uint32_t sbX = sb + WX1 * 4;

    const int tid  = threadIdx.x;
    const int lane = tid & 31;
    const int wid  = tid >> 5;       // 0..7
    const int lq   = lane >> 2;
    const int lr   = lane & 3;
    const int wn   = wid;

    const int row0 = blockIdx.x * 32;
    const int bb   = row0 / PS;
    const int s0   = row0 % PS;

    if (tid == 0) {
        const int* p32 = (const int*)indices_raw;
        int is64 = 1;
        #pragma unroll
        for (int t = 0; t < 32; t++)
            if (p32[2 * t + 1] != 0) { is64 = 0; break; }
        *(int*)(smw + WMODE) = is64;
    }
    for (int i = tid; i < 512; i += 256) b1s[i] = b1[i];
    b2s[tid] = b2[tid];
    w3s[tid] = W3[tid];
    __syncthreads();

    const int is64 = *(const int*)(smw + WMODE);
    if (tid < 128) {
        const int m = tid >> 2, j = tid & 3;
        const long long e = ((long long)(bb * PS + s0 + m)) * 4 + j;
        int idx;
        if (is64) idx = (int)((const long long*)indices_raw)[e];
        else      idx = ((const int*)indices_raw)[e];
        nodes[m * 4 + j] = bb * PN + (idx & (PN - 1));
    }
    __syncthreads();

    auto issueB2 = [&](int buf, int kt) {
        #pragma unroll
        for (int i = 0; i < 8; i++) {
            const int idx = i * 256 + tid;
            const int n = idx >> 3, g = idx & 7;
            cp16(sbB + buf * 32768 + (uint32_t)t64w(n, g) * 4,
                 g_W2t + (size_t)n * K2 + kt + g * 8);
        }
    };

    // gather state: this thread sums 8 cols of one row per chunk
    const int rg = tid >> 3;      // row 0..31
    const int l8 = tid & 7;
    const __half* gbases[4];
    #pragma unroll
    for (int j = 0; j < 4; j++)
        gbases[j] = g_Y + (size_t)nodes[rg * 4 + j] * 2048 + j * 512 + l8 * 8;

    auto gather_chunk = [&](int i) {
        uint4 v[4];
        #pragma unroll
        for (int j = 0; j < 4; j++)
            v[j] = __ldg((const uint4*)(gbases[j] + i * 64));
        const int col0 = i * 64 + l8 * 8;
        const int kp0  = col0 >> 1;
        #pragma unroll
        for (int p = 0; p < 4; p++) {
            const float2 f0 = __half22float2(((const __half2*)&v[0])[p]);
            const float2 f1 = __half22float2(((const __half2*)&v[1])[p]);
            const float2 f2 = __half22float2(((const __half2*)&v[2])[p]);
            const float2 f3 = __half22float2(((const __half2*)&v[3])[p]);
            const float sx = (f0.x + f1.x) + (f2.x + f3.x);
            const float sy = (f0.y + f1.y) + (f2.y + f3.y);
            const float g0 = gelu_exact(sx + b1s[col0 + 2 * p]);
            const float g1 = gelu_exact(sy + b1s[col0 + 2 * p + 1]);
            const __half2 hh = __floats2half2_rn(g0, g1);
            smw[WX1 + xwd_w(rg, kp0 + p)] = *(const uint32_t*)&hh;
        }
    };

    // prime: W2 stages 0/1 in flight, x1 chunk 0 gathered
    issueB2(0, 0);  CP_COMMIT();
    issueB2(1, 64); CP_COMMIT();
    gather_chunk(0);

    // ---------------- fused mainloop: 8 stages ------------------------------
    const int arow = lane & 15;
    const int l7   = lane & 7;
    const int gha  = lane >> 4;
    const int ghb  = (lane >> 3) & 1;
    const int bn2  = wn * 32 + ((lane >> 4) << 3) + (lane & 7);
    const uint32_t bbase0 = (uint32_t)(bn2 * 32) * 4;

    float acc2[2][4][4];
    #pragma unroll
    for (int mf = 0; mf < 2; mf++)
        #pragma unroll
        for (int nf = 0; nf < 4; nf++)
            #pragma unroll
            for (int q = 0; q < 4; q++) acc2[mf][nf][q] = 0.0f;

    const int NST2 = K2 / 64;   // 8
    for (int s = 0; s < NST2; ++s) {
        CP_WAIT(1);
        __syncthreads();   // W2 stage s ready; x1 chunk s stores visible

        if (s + 1 < NST2) gather_chunk(s + 1);   // overlaps with stage-s MMAs

        const uint32_t Bb = sbB + (s & 1) * 32768;
        #pragma unroll
        for (int ks = 0; ks < 4; ++ks) {
            const int gb = s * 8 + ks * 2 + gha;
            uint32_t a[2][4];
            {
                const int r = arow;
                ldsm4(a[0], sbX + (uint32_t)(r * 256 + ((gb * 4) ^ ((r & 7) << 2))) * 4);
                const int r2 = arow + 16;
                ldsm4(a[1], sbX + (uint32_t)(r2 * 256 + ((gb * 4) ^ ((r2 & 7) << 2))) * 4);
            }
            const int sbo = ((2 * ks + ghb) ^ l7) * 16;
            uint32_t bf[4][2];
            {
                uint32_t t4[4];
                ldsm4(t4, Bb + bbase0 + sbo);
                bf[0][0] = t4[0]; bf[0][1] = t4[1];
                bf[1][0] = t4[2]; bf[1][1] = t4[3];
                ldsm4(t4, Bb + bbase0 + 16 * 128 + sbo);
                bf[2][0] = t4[0]; bf[2][1] = t4[1];
                bf[3][0] = t4[2]; bf[3][1] = t4[3];
            }
            #pragma unroll
            for (int nf = 0; nf < 4; nf++) {
                mma_f16(acc2[0][nf], a[0], bf[nf]);
                mma_f16(acc2[1][nf], a[1], bf[nf]);
            }
        }
        __syncthreads();   // buffer s&1 consumed; chunk s+1 published for next
        if (s + 2 < NST2) issueB2((s + 2) & 1, (s + 2) * 64);
        CP_COMMIT();       // unconditional: stage s <-> group s invariant
    }

    const float b3v = b3[0];
    #pragma unroll
    for (int mf = 0; mf < 2; mf++) {
        float p0 = 0.0f, p1 = 0.0f;
        #pragma unroll
        for (int nf = 0; nf < 4; nf++) {
            const int col = wn * 32 + nf * 8 + 2 * lr;
            const float* c = acc2[mf][nf];
            p0 = fmaf(gelu_exact(c[0] + b2s[col]),     w3s[col],     p0);
            p0 = fmaf(gelu_exact(c[1] + b2s[col + 1]), w3s[col + 1], p0);
            p1 = fmaf(gelu_exact(c[2] + b2s[col]),     w3s[col],     p1);
            p1 = fmaf(gelu_exact(c[3] + b2s[col + 1]), w3s[col + 1], p1);
        }
        p0 += __shfl_xor_sync(0xffffffffu, p0, 1);
        p0 += __shfl_xor_sync(0xffffffffu, p0, 2);
        p1 += __shfl_xor_sync(0xffffffffu, p1, 1);
        p1 += __shfl_xor_sync(0xffffffffu, p1, 2);
        if (lr == 0) {
            const int r0 = mf * 16 + lq;
            red[r0 * 8 + wn]       = p0;
            red[(r0 + 8) * 8 + wn] = p1;
        }
    }
    __syncthreads();

    if (tid < 32) {
        const float* rr = &red[tid * 8];
        const float ssum = rr[0] + rr[1] + rr[2] + rr[3] + rr[4] + rr[5] + rr[6] + rr[7];
        out[row0 + tid] = softplus_stable(ssum + b3v);
    }
}

extern "C" void kernel_launch(void* const* d_in, const int* in_sizes, int n_in,
                              void* d_out, int out_size)
{
    const float* h   = (const float*)d_in[0];
    const void*  idx = (const void*)d_in[1];
    const float* W1  = (const float*)d_in[2];
    const float* b1  = (const float*)d_in[3];
    const float* W2  = (const float*)d_in[4];
    const float* b2  = (const float*)d_in[5];
    const float* W3  = (const float*)d_in[6];
    const float* b3  = (const float*)d_in[7];
    float*       out = (float*)d_out;

    void *ph, *pw1, *pw2;
    cudaGetSymbolAddress(&ph,  g_h);
    cudaGetSymbolAddress(&pw1, g_W1t);
    cudaGetSymbolAddress(&pw2, g_W2t);

    cvt_h_kernel<<<2048, 256>>>((__half*)ph, h, PB * PN * PD / 4);
    transpose_half_kernel<<<dim3(N1 / 32, K1 / 32), dim3(32, 8)>>>((__half*)pw1, W1, K1, N1);
    transpose_half_kernel<<<dim3(N2 / 32, K2 / 32), dim3(32, 8)>>>((__half*)pw2, W2, K2, N2);

    cudaFuncSetAttribute(precompute_y_kernel,
                         cudaFuncAttributeMaxDynamicSharedMemorySize, PRE_SMEM_BYTES);
    precompute_y_kernel<<<dim3(PB * PN / 128, 8), 512, PRE_SMEM_BYTES>>>();

    cudaFuncSetAttribute(swap_scoring_g,
                         cudaFuncAttributeMaxDynamicSharedMemorySize, SC_SMEM_BYTES);
    swap_scoring_g<<<NROWS / 32, 256, SC_SMEM_BYTES>>>(
        idx, b1, b2, W3, b3, out);
}